// round 15
// baseline (speedup 1.0000x reference)
#include <cuda_runtime.h>

#define NL 25
#define ED 64
#define HD 8
#define NB 1000
#define NS 512
#define CS 5          // CTAs (batch slices) per layer
#define BPC 200       // batch elements per CTA
#define TPB 800       // 4 threads per batch element; 25 full warps

typedef unsigned long long u64;

// Scratch (static __device__ arrays; allocation-free per harness rules)
__device__ float g_xproj[NS * NB * 24];                    // layer-0 x-projections (+bias)
__device__ float g_hbuf[(NL - 1) * NS * NB * HD];          // inter-layer h buffers
__device__ unsigned int g_cnt[(NL - 1) * NB];              // per-(layer,b) progress counters

// ---------- f32x2 packed helpers ----------
__device__ __forceinline__ u64 pk2(float v) {
    u64 d; asm("mov.b64 %0,{%1,%1};" : "=l"(d) : "f"(v)); return d;
}
__device__ __forceinline__ u64 pkab(float a, float b) {
    u64 d; asm("mov.b64 %0,{%1,%2};" : "=l"(d) : "f"(a), "f"(b)); return d;
}
__device__ __forceinline__ void upk(u64 v, float& a, float& b) {
    asm("mov.b64 {%0,%1},%2;" : "=f"(a), "=f"(b) : "l"(v));
}
__device__ __forceinline__ u64 f2fma(u64 a, u64 b, u64 c) {
    u64 d; asm("fma.rn.f32x2 %0,%1,%2,%3;" : "=l"(d) : "l"(a), "l"(b), "l"(c)); return d;
}
__device__ __forceinline__ u64 f2add(u64 a, u64 b) {
    u64 d; asm("add.rn.f32x2 %0,%1,%2;" : "=l"(d) : "l"(a), "l"(b)); return d;
}
__device__ __forceinline__ u64 f2mul(u64 a, u64 b) {
    u64 d; asm("mul.rn.f32x2 %0,%1,%2;" : "=l"(d) : "l"(a), "l"(b)); return d;
}
// acc[0..1] (quad of 4 cols) += s2 * w[0..3]  (1x LDS.128)
__device__ __forceinline__ void fma4w(u64* acc, u64 s2, const float* w4) {
    ulonglong2 w = *(const ulonglong2*)(w4);
    acc[0] = f2fma(s2, w.x, acc[0]); acc[1] = f2fma(s2, w.y, acc[1]);
}
// full-row version (precompute kernel)
__device__ __forceinline__ void fma8w(u64* acc, u64 s2, const float* wrow) {
    ulonglong2 w01 = *(const ulonglong2*)(wrow);
    ulonglong2 w23 = *(const ulonglong2*)(wrow + 4);
    acc[0] = f2fma(s2, w01.x, acc[0]); acc[1] = f2fma(s2, w01.y, acc[1]);
    acc[2] = f2fma(s2, w23.x, acc[2]); acc[3] = f2fma(s2, w23.y, acc[3]);
}

// ---------- MUFU.TANH activations ----------
__device__ __forceinline__ float tanh_hw(float x) {
    float t; asm("tanh.approx.f32 %0,%1;" : "=f"(t) : "f"(x)); return t;
}
__device__ __forceinline__ float sigm(float x) {
    return fmaf(0.5f, tanh_hw(0.5f * x), 0.5f);
}

__device__ __forceinline__ unsigned int acq_ld(const unsigned int* p) {
    unsigned int v;
    asm volatile("ld.global.acquire.gpu.b32 %0, [%1];" : "=r"(v) : "l"(p) : "memory");
    return v;
}
__device__ __forceinline__ u64 shx(u64 v, int lanemask) {
    return __shfl_xor_sync(0xffffffffu, v, lanemask);
}

// ---------- precompute: layer-0 x-projections + counter clear ----------
__global__ void __launch_bounds__(256) precompute_xproj(
    const int* __restrict__ x, const float* __restrict__ emb,
    const float* __restrict__ Wxz0, const float* __restrict__ bz0,
    const float* __restrict__ Wxr0, const float* __restrict__ br0,
    const float* __restrict__ WxH0, const float* __restrict__ bH0)
{
    __shared__ __align__(16) float sw[3][ED][8];
    __shared__ __align__(16) float sb[24];
    const int tid = threadIdx.x;
    for (int i = tid; i < ED * HD; i += blockDim.x) {
        ((float*)sw[0])[i] = Wxz0[i];
        ((float*)sw[1])[i] = Wxr0[i];
        ((float*)sw[2])[i] = WxH0[i];
    }
    if (tid < 8) { sb[tid] = bz0[tid]; sb[8 + tid] = br0[tid]; sb[16 + tid] = bH0[tid]; }
    __syncthreads();

    const int gid = blockIdx.x * blockDim.x + tid;   // NB*NS = 512000 threads

    if (gid < (NL - 1) * NB / 4) {
        ((uint4*)g_cnt)[gid] = make_uint4(0u, 0u, 0u, 0u);
    }

    if (gid >= NB * NS) return;
    const int b = gid / NS, t = gid % NS;
    const int idx = x[gid];
    const float4* e4 = (const float4*)(emb + (long long)idx * ED);

    const u64* sb2 = (const u64*)sb;
    u64 acc[12];
    #pragma unroll
    for (int j = 0; j < 12; j++) acc[j] = sb2[j];

    #pragma unroll
    for (int k4 = 0; k4 < ED / 4; k4++) {
        float4 ev = e4[k4];
        float es[4] = {ev.x, ev.y, ev.z, ev.w};
        #pragma unroll
        for (int q = 0; q < 4; q++) {
            const int k = k4 * 4 + q;
            const u64 s2 = pk2(es[q]);
            fma8w(acc,     s2, sw[0][k]);
            fma8w(acc + 4, s2, sw[1][k]);
            fma8w(acc + 8, s2, sw[2][k]);
        }
    }
    float o[24];
    #pragma unroll
    for (int j = 0; j < 12; j++) upk(acc[j], o[2 * j], o[2 * j + 1]);
    float4* o4 = (float4*)(g_xproj + ((long long)t * NB + b) * 24);
    #pragma unroll
    for (int j = 0; j < 6; j++)
        o4[j] = make_float4(o[4 * j], o[4 * j + 1], o[4 * j + 2], o[4 * j + 3]);
}

// ---------- persistent layer-pipelined GRU, 4-thread quad split ----------
// Thread q: owns cols 2q..2q+1; accumulates col-quad Q=q>>1 over k-half K=q&1.
// Gate combine: one shfl_xor(1)+add (other-slot send). r/h k-half quads via
// xor-1/xor-2 ladder with uniform selects. All indexing static/uniform.
__global__ void __launch_bounds__(TPB, 1) gru_pipeline(
    const float* __restrict__ Whz0, const float* __restrict__ Whr0, const float* __restrict__ WrH0,
    const float* __restrict__ Wxz, const float* __restrict__ Whz, const float* __restrict__ bz,
    const float* __restrict__ Wxr, const float* __restrict__ Whr, const float* __restrict__ br,
    const float* __restrict__ WxH, const float* __restrict__ WrH, const float* __restrict__ bH,
    const float* __restrict__ Why, const float* __restrict__ by,
    float* __restrict__ out, int out_size)
{
    __shared__ __align__(16) float sw[6][HD][8];  // 0 Wxz | 1 Whz | 2 Wxr | 3 Whr | 4 WxH | 5 WrH
    __shared__ __align__(16) float sb[24];
    const int tid = threadIdx.x;
    const int layer = blockIdx.x / CS;
    const int c = blockIdx.x % CS;

    if (layer == 0) {
        for (int i = tid; i < HD * HD; i += blockDim.x) {
            ((float*)sw[1])[i] = Whz0[i];   // slot 1 = Whz0
            ((float*)sw[3])[i] = Whr0[i];   // slot 3 = Whr0
            ((float*)sw[5])[i] = WrH0[i];   // slot 5 = WrH0
        }
        if (tid < 24) sb[tid] = 0.f;
    } else {
        const int off = (layer - 1) * HD * HD;
        for (int i = tid; i < HD * HD; i += blockDim.x) {
            ((float*)sw[0])[i] = Wxz[off + i];
            ((float*)sw[1])[i] = Whz[off + i];
            ((float*)sw[2])[i] = Wxr[off + i];
            ((float*)sw[3])[i] = Whr[off + i];
            ((float*)sw[4])[i] = WxH[off + i];
            ((float*)sw[5])[i] = WrH[off + i];
        }
        if (tid < 8) {
            sb[tid]      = bz[(layer - 1) * 8 + tid];
            sb[8 + tid]  = br[(layer - 1) * 8 + tid];
            sb[16 + tid] = bH[(layer - 1) * 8 + tid];
        }
    }
    __syncthreads();

    const int p = tid >> 2;                  // batch element within CTA (0..199)
    const int q = tid & 3;
    const int s = q & 1;                     // slot within quad / k-half K
    const int Q = q >> 1;                    // accumulated col-quad
    const bool keep = (s == Q);              // q in {0,3}: own quad == k-half quad
    const int b = c * BPC + p;
    const bool storer = (q == 0);

    // weight base pointers: row base = k-half start (4*s rows), col base = 4*Q
    const int wb = 32 * s + 4 * Q;
    const float* WXZp = (const float*)sw[0] + wb;
    const float* WHZp = (const float*)sw[1] + wb;
    const float* WXRp = (const float*)sw[2] + wb;
    const float* WHRp = (const float*)sw[3] + wb;
    const float* WXHp = (const float*)sw[4] + wb;
    const float* WRHp = (const float*)sw[5] + wb;

    // own-2-col biases (zero for layer 0)
    const u64 bzr = ((const u64*)sb)[q];
    const u64 brr = ((const u64*)sb)[4 + q];
    const u64 bHr = ((const u64*)sb)[8 + q];

    float hq0 = 0.f, hq1 = 0.f, hq2 = 0.f, hq3 = 0.f;   // h quad K (k-half inputs)
    float ho0 = 0.f, ho1 = 0.f;                         // own 2 h cols

    unsigned int* pcnt = (layer < NL - 1) ? g_cnt + layer * NB + b : 0;
    float* outp = (layer < NL - 1)
        ? g_hbuf + (((long long)layer * NS) * NB + b) * HD : 0;

    const bool producer = (layer < NL - 1);
    u64 fh0 = 0, fh1 = 0, fh2 = 0, fh3 = 0;   // full-h assembly (quad0 u64x2, quad1 u64x2)

    if (layer == 0) {
        // -------- layer 0: precomputed x-projections (own 2 cols), no polling -----
        const float* xp = g_xproj + (long long)b * 24 + 2 * q;
        float2 vz = *(const float2*)(xp);
        float2 vr = *(const float2*)(xp + 8);
        float2 vH = *(const float2*)(xp + 16);
        xp += NB * 24;

        #pragma unroll 1
        for (int t = 0; t < NS; t++) {
            float2 nvz, nvr, nvH;
            if (t + 1 < NS) {
                nvz = *(const float2*)(xp);
                nvr = *(const float2*)(xp + 8);
                nvH = *(const float2*)(xp + 16);
                xp += NB * 24;
            }
            // gate accums over quad Q; own slot initialized with xproj (incl bias)
            const u64 xz = pkab(vz.x, vz.y), xr = pkab(vr.x, vr.y), xH = pkab(vH.x, vH.y);
            u64 az[2], ar[2], aH[2];
            az[0] = s ? 0 : xz; az[1] = s ? xz : 0;
            ar[0] = s ? 0 : xr; ar[1] = s ? xr : 0;
            aH[0] = s ? 0 : xH; aH[1] = s ? xH : 0;
            const float hk[4] = {hq0, hq1, hq2, hq3};
            #pragma unroll
            for (int j = 0; j < 4; j++) {
                const u64 h2 = pk2(hk[j]);
                fma4w(az, h2, WHZp + j * 8);
                fma4w(ar, h2, WHRp + j * 8);
            }
            // combine z, r (send other slot)
            u64 azown = f2add(s ? az[1] : az[0], shx(s ? az[0] : az[1], 1));
            u64 arown = f2add(s ? ar[1] : ar[0], shx(s ? ar[0] : ar[1], 1));
            float zf0, zf1, rf0, rf1;
            upk(azown, zf0, zf1); upk(arown, rf0, rf1);
            const float z0 = sigm(zf0), z1 = sigm(zf1);
            const float r0 = sigm(rf0), r1 = sigm(rf1);
            // r -> k-half quad
            u64 r01 = pkab(r0, r1);
            u64 rp = shx(r01, 1);
            u64 rq0 = s ? rp : r01, rq1 = s ? r01 : rp;      // quad Q
            u64 rr0 = shx(rq0, 2), rr1 = shx(rq1, 2);        // quad 1-Q
            u64 rk0 = keep ? rq0 : rr0, rk1 = keep ? rq1 : rr1;
            // rh over own k-half
            u64 rh01 = f2mul(pkab(hq0, hq1), rk0);
            u64 rh23 = f2mul(pkab(hq2, hq3), rk1);
            float rh[4]; upk(rh01, rh[0], rh[1]); upk(rh23, rh[2], rh[3]);
            #pragma unroll
            for (int j = 0; j < 4; j++) fma4w(aH, pk2(rh[j]), WRHp + j * 8);
            u64 aHown = f2add(s ? aH[1] : aH[0], shx(s ? aH[0] : aH[1], 1));
            float hf0, hf1; upk(aHown, hf0, hf1);
            const float hn0 = fmaf(z0, tanh_hw(hf0) - ho0, ho0);
            const float hn1 = fmaf(z1, tanh_hw(hf1) - ho1, ho1);
            // h exchange ladder
            u64 h01 = pkab(hn0, hn1);
            u64 hp = shx(h01, 1);
            u64 hs0 = s ? hp : h01, hs1 = s ? h01 : hp;      // quad Q
            u64 hx0 = shx(hs0, 2), hx1 = shx(hs1, 2);        // quad 1-Q
            u64 hk0 = keep ? hs0 : hx0, hk1 = keep ? hs1 : hx1;
            upk(hk0, hq0, hq1); upk(hk1, hq2, hq3);
            ho0 = hn0; ho1 = hn1;
            fh0 = hs0; fh1 = hs1; fh2 = hx0; fh3 = hx1;
            if (storer) {
                float a0, a1, a2, a3, c0, c1, c2, c3;
                upk(hs0, a0, a1); upk(hs1, a2, a3);
                upk(hx0, c0, c1); upk(hx1, c2, c3);
                ((float4*)outp)[0] = make_float4(a0, a1, a2, a3);
                ((float4*)outp)[1] = make_float4(c0, c1, c2, c3);
                asm volatile("st.global.release.gpu.b32 [%0], %1;"
                             :: "l"(pcnt), "r"((unsigned int)(t + 1)) : "memory");
            }
            outp += NB * HD;
            vz = nvz; vr = nvr; vH = nvH;
        }
    } else {
        // -------- layers 1..24: watermark consume, fused x+h quad step --------
        const unsigned int* ccnt = g_cnt + (layer - 1) * NB + b;
        const float* inp = g_hbuf + (((long long)(layer - 1) * NS) * NB + b) * HD + 4 * s;
        unsigned int avail = 0;

        float4 xc, xn;
        {
            while (avail < 1u) avail = acq_ld(ccnt);
            xc = __ldcg((const float4*)inp);
            inp += NB * HD;
            while (avail < 2u) avail = acq_ld(ccnt);
            xn = __ldcg((const float4*)inp);
            inp += NB * HD;
        }

        #pragma unroll 1
        for (int t = 0; t < NS; t++) {
            // early-issue counter load
            const unsigned int want = (unsigned int)(t + 3);
            const bool needp = (t + 2 < NS) && (avail < want);
            unsigned int cv = 0;
            if (needp) cv = acq_ld(ccnt);

            // gate accums over quad Q (x + h fused, own k-half)
            u64 az[2], ar[2], aH[2];
            az[0] = s ? 0 : bzr; az[1] = s ? bzr : 0;
            ar[0] = s ? 0 : brr; ar[1] = s ? brr : 0;
            aH[0] = s ? 0 : bHr; aH[1] = s ? bHr : 0;
            const float xk[4] = {xc.x, xc.y, xc.z, xc.w};
            const float hk[4] = {hq0, hq1, hq2, hq3};
            #pragma unroll
            for (int j = 0; j < 4; j++) {
                const u64 x2 = pk2(xk[j]);
                const u64 h2 = pk2(hk[j]);
                fma4w(az, x2, WXZp + j * 8);
                fma4w(az, h2, WHZp + j * 8);
                fma4w(ar, x2, WXRp + j * 8);
                fma4w(ar, h2, WHRp + j * 8);
                fma4w(aH, x2, WXHp + j * 8);
            }
            // late check + prefetch x(t+2) (off the gate chain)
            float4 xf;
            if (t + 2 < NS) {
                if (needp) {
                    while (cv < want) cv = acq_ld(ccnt);
                    avail = cv;
                }
                xf = __ldcg((const float4*)inp);
                inp += NB * HD;
            }
            // combine z, r
            u64 azown = f2add(s ? az[1] : az[0], shx(s ? az[0] : az[1], 1));
            u64 arown = f2add(s ? ar[1] : ar[0], shx(s ? ar[0] : ar[1], 1));
            float zf0, zf1, rf0, rf1;
            upk(azown, zf0, zf1); upk(arown, rf0, rf1);
            const float z0 = sigm(zf0), z1 = sigm(zf1);
            const float r0 = sigm(rf0), r1 = sigm(rf1);
            // r -> k-half quad
            u64 r01 = pkab(r0, r1);
            u64 rp = shx(r01, 1);
            u64 rq0 = s ? rp : r01, rq1 = s ? r01 : rp;
            u64 rr0 = shx(rq0, 2), rr1 = shx(rq1, 2);
            u64 rk0 = keep ? rq0 : rr0, rk1 = keep ? rq1 : rr1;
            u64 rh01 = f2mul(pkab(hq0, hq1), rk0);
            u64 rh23 = f2mul(pkab(hq2, hq3), rk1);
            float rh[4]; upk(rh01, rh[0], rh[1]); upk(rh23, rh[2], rh[3]);
            #pragma unroll
            for (int j = 0; j < 4; j++) fma4w(aH, pk2(rh[j]), WRHp + j * 8);
            u64 aHown = f2add(s ? aH[1] : aH[0], shx(s ? aH[0] : aH[1], 1));
            float hf0, hf1; upk(aHown, hf0, hf1);
            const float hn0 = fmaf(z0, tanh_hw(hf0) - ho0, ho0);
            const float hn1 = fmaf(z1, tanh_hw(hf1) - ho1, ho1);
            // h exchange ladder
            u64 h01 = pkab(hn0, hn1);
            u64 hp = shx(h01, 1);
            u64 hs0 = s ? hp : h01, hs1 = s ? h01 : hp;
            u64 hx0 = shx(hs0, 2), hx1 = shx(hs1, 2);
            u64 hk0 = keep ? hs0 : hx0, hk1 = keep ? hs1 : hx1;
            upk(hk0, hq0, hq1); upk(hk1, hq2, hq3);
            ho0 = hn0; ho1 = hn1;
            fh0 = hs0; fh1 = hs1; fh2 = hx0; fh3 = hx1;
            if (producer) {
                if (storer) {
                    float a0, a1, a2, a3, c0, c1, c2, c3;
                    upk(hs0, a0, a1); upk(hs1, a2, a3);
                    upk(hx0, c0, c1); upk(hx1, c2, c3);
                    ((float4*)outp)[0] = make_float4(a0, a1, a2, a3);
                    ((float4*)outp)[1] = make_float4(c0, c1, c2, c3);
                    asm volatile("st.global.release.gpu.b32 [%0], %1;"
                                 :: "l"(pcnt), "r"((unsigned int)(t + 1)) : "memory");
                }
                outp += NB * HD;
            }
            xc = xn; xn = xf;
        }
    }

    // final outputs (thread q==0 holds full h in fh0..fh3)
    if (storer) {
        float a0, a1, a2, a3, c0, c1, c2, c3;
        upk(fh0, a0, a1); upk(fh1, a2, a3);
        upk(fh2, c0, c1); upk(fh3, c2, c3);
        if (out_size >= NB + NL * NB * HD) {
            float4* hpt = (float4*)(out + NB + ((long long)layer * NB + b) * HD);
            hpt[0] = make_float4(a0, a1, a2, a3);
            hpt[1] = make_float4(c0, c1, c2, c3);
        }
        if (layer == NL - 1) {
            float acc = by[0];
            acc = fmaf(a0, Why[0], acc); acc = fmaf(a1, Why[1], acc);
            acc = fmaf(a2, Why[2], acc); acc = fmaf(a3, Why[3], acc);
            acc = fmaf(c0, Why[4], acc); acc = fmaf(c1, Why[5], acc);
            acc = fmaf(c2, Why[6], acc); acc = fmaf(c3, Why[7], acc);
            out[b] = acc;
        }
    }
}

extern "C" void kernel_launch(void* const* d_in, const int* in_sizes, int n_in,
                              void* d_out, int out_size) {
    const int*   x    = (const int*)d_in[0];
    const float* emb  = (const float*)d_in[1];
    const float* Wxz0 = (const float*)d_in[2];
    const float* Whz0 = (const float*)d_in[3];
    const float* bz0  = (const float*)d_in[4];
    const float* Wxr0 = (const float*)d_in[5];
    const float* Whr0 = (const float*)d_in[6];
    const float* br0  = (const float*)d_in[7];
    const float* WxH0 = (const float*)d_in[8];
    const float* WrH0 = (const float*)d_in[9];
    const float* bH0  = (const float*)d_in[10];
    const float* Wxz  = (const float*)d_in[11];
    const float* Whz  = (const float*)d_in[12];
    const float* bz   = (const float*)d_in[13];
    const float* Wxr  = (const float*)d_in[14];
    const float* Whr  = (const float*)d_in[15];
    const float* br   = (const float*)d_in[16];
    const float* WxH  = (const float*)d_in[17];
    const float* WrH  = (const float*)d_in[18];
    const float* bH   = (const float*)d_in[19];
    const float* Why  = (const float*)d_in[20];
    const float* by   = (const float*)d_in[21];
    float* out = (float*)d_out;

    precompute_xproj<<<(NB * NS + 255) / 256, 256>>>(x, emb, Wxz0, bz0, Wxr0, br0, WxH0, bH0);
    gru_pipeline<<<NL * CS, TPB>>>(Whz0, Whr0, WrH0,
                                   Wxz, Whz, bz, Wxr, Whr, br, WxH, WrH, bH,
                                   Why, by, out, out_size);
}

// round 17
// speedup vs baseline: 4.5135x; 4.5135x over previous
#include <cuda_runtime.h>

#define NL 25
#define ED 64
#define HD 8
#define NB 1000
#define NS 512
#define NBCR 7                          // real batch columns per CTA
#define GRID ((NB + NBCR - 1) / NBCR)   // 143 independent CTAs
#define TPB (NL * 8)                    // 200 threads: (layer, col)
#define WST 392                         // per-layer weight stride (floats): 6*64 + 8 pad

typedef unsigned long long u64;

// Scratch (static __device__; allocation-free per harness rules)
__device__ float g_xproj[NS * NB * 24];   // layer-0 x-projections (+bias)

// ---------- f32x2 packed helpers ----------
__device__ __forceinline__ u64 pk2(float v) {
    u64 d; asm("mov.b64 %0,{%1,%1};" : "=l"(d) : "f"(v)); return d;
}
__device__ __forceinline__ u64 pkab(float a, float b) {
    u64 d; asm("mov.b64 %0,{%1,%2};" : "=l"(d) : "f"(a), "f"(b)); return d;
}
__device__ __forceinline__ void upk(u64 v, float& a, float& b) {
    asm("mov.b64 {%0,%1},%2;" : "=f"(a), "=f"(b) : "l"(v));
}
__device__ __forceinline__ u64 f2fma(u64 a, u64 b, u64 c) {
    u64 d; asm("fma.rn.f32x2 %0,%1,%2,%3;" : "=l"(d) : "l"(a), "l"(b), "l"(c)); return d;
}
// acc[0..3] (8 cols) += s2 * wrow[0..7]  (2x LDS.128)
__device__ __forceinline__ void fma8w(u64* acc, u64 s2, const float* wrow) {
    ulonglong2 w01 = *(const ulonglong2*)(wrow);
    ulonglong2 w23 = *(const ulonglong2*)(wrow + 4);
    acc[0] = f2fma(s2, w01.x, acc[0]); acc[1] = f2fma(s2, w01.y, acc[1]);
    acc[2] = f2fma(s2, w23.x, acc[2]); acc[3] = f2fma(s2, w23.y, acc[3]);
}

// ---------- MUFU.TANH activations ----------
__device__ __forceinline__ float tanh_hw(float x) {
    float t; asm("tanh.approx.f32 %0,%1;" : "=f"(t) : "f"(x)); return t;
}
__device__ __forceinline__ float sigm(float x) {
    return fmaf(0.5f, tanh_hw(0.5f * x), 0.5f);
}

// ---------- precompute: layer-0 x-projections ----------
__global__ void __launch_bounds__(256) precompute_xproj(
    const int* __restrict__ x, const float* __restrict__ emb,
    const float* __restrict__ Wxz0, const float* __restrict__ bz0,
    const float* __restrict__ Wxr0, const float* __restrict__ br0,
    const float* __restrict__ WxH0, const float* __restrict__ bH0)
{
    __shared__ __align__(16) float sw[3][ED][8];
    __shared__ __align__(16) float sb[24];
    const int tid = threadIdx.x;
    for (int i = tid; i < ED * HD; i += blockDim.x) {
        ((float*)sw[0])[i] = Wxz0[i];
        ((float*)sw[1])[i] = Wxr0[i];
        ((float*)sw[2])[i] = WxH0[i];
    }
    if (tid < 8) { sb[tid] = bz0[tid]; sb[8 + tid] = br0[tid]; sb[16 + tid] = bH0[tid]; }
    __syncthreads();

    const int gid = blockIdx.x * blockDim.x + tid;   // NB*NS = 512000 threads
    if (gid >= NB * NS) return;
    const int b = gid / NS, t = gid % NS;
    const int idx = x[gid];
    const float4* e4 = (const float4*)(emb + (long long)idx * ED);

    const u64* sb2 = (const u64*)sb;
    u64 acc[12];
    #pragma unroll
    for (int j = 0; j < 12; j++) acc[j] = sb2[j];

    #pragma unroll
    for (int k4 = 0; k4 < ED / 4; k4++) {
        float4 ev = e4[k4];
        float es[4] = {ev.x, ev.y, ev.z, ev.w};
        #pragma unroll
        for (int q = 0; q < 4; q++) {
            const int k = k4 * 4 + q;
            const u64 s2 = pk2(es[q]);
            fma8w(acc,     s2, sw[0][k]);
            fma8w(acc + 4, s2, sw[1][k]);
            fma8w(acc + 8, s2, sw[2][k]);
        }
    }
    float o[24];
    #pragma unroll
    for (int j = 0; j < 12; j++) upk(acc[j], o[2 * j], o[2 * j + 1]);
    float4* o4 = (float4*)(g_xproj + ((long long)t * NB + b) * 24);
    #pragma unroll
    for (int j = 0; j < 6; j++)
        o4[j] = make_float4(o[4 * j], o[4 * j + 1], o[4 * j + 2], o[4 * j + 3]);
}

// ---------- wavefront GRU: one CTA = all 25 layers x 7 batch elements ----------
// Thread (l, col). Iteration i: thread l computes its step t = i - l.
// Inter-layer handoff via single-buffered smem + two __syncthreads per iter.
__global__ void __launch_bounds__(TPB, 1) gru_wave(
    const float* __restrict__ Whz0, const float* __restrict__ Whr0, const float* __restrict__ WrH0,
    const float* __restrict__ Wxz, const float* __restrict__ Whz, const float* __restrict__ bz,
    const float* __restrict__ Wxr, const float* __restrict__ Whr, const float* __restrict__ br,
    const float* __restrict__ WxH, const float* __restrict__ WrH, const float* __restrict__ bH,
    const float* __restrict__ Why, const float* __restrict__ by,
    float* __restrict__ out, int out_size)
{
    // weights: per-layer block of WST floats; slots m*64: 0 Wxz | 1 Whz | 2 Wxr | 3 Whr | 4 WxH | 5 WrH
    __shared__ __align__(16) float sw[NL * WST];     // 39.2 KB
    __shared__ __align__(16) float shb[NL * 64];     // 6.4 KB: h handoff [l][col][8]
    const int tid = threadIdx.x;

    // load weights (layers 1..24)
    for (int i = tid; i < 24 * 64; i += TPB) {
        const int ll = i >> 6, idx = i & 63;
        float* dl = sw + (ll + 1) * WST;
        dl[idx]        = Wxz[i];
        dl[64 + idx]   = Whz[i];
        dl[128 + idx]  = Wxr[i];
        dl[192 + idx]  = Whr[i];
        dl[256 + idx]  = WxH[i];
        dl[320 + idx]  = WrH[i];
    }
    // layer 0: only h-side matrices (x side lives in g_xproj)
    for (int i = tid; i < 64; i += TPB) {
        sw[64 + i]  = Whz0[i];
        sw[192 + i] = Whr0[i];
        sw[320 + i] = WrH0[i];
    }
    __syncthreads();

    const int l = tid >> 3;              // 0..24
    const int col = tid & 7;             // 0..7 (7 = padding column)
    const int b = blockIdx.x * NBCR + col;
    const bool bok = (col < NBCR) && (b < NB);
    const float* wb = sw + l * WST;

    // biases in registers (zero for layer 0 — folded into xproj)
    u64 b2[12];
    if (l >= 1) {
        const float* pz = bz + (l - 1) * 8;
        const float* pr = br + (l - 1) * 8;
        const float* pH = bH + (l - 1) * 8;
        #pragma unroll
        for (int j = 0; j < 4; j++) {
            b2[j]     = pkab(pz[2 * j], pz[2 * j + 1]);
            b2[4 + j] = pkab(pr[2 * j], pr[2 * j + 1]);
            b2[8 + j] = pkab(pH[2 * j], pH[2 * j + 1]);
        }
    } else {
        #pragma unroll
        for (int j = 0; j < 12; j++) b2[j] = 0ull;
    }

    float h[8];
    #pragma unroll
    for (int j = 0; j < 8; j++) h[j] = 0.f;

    // layer-0 xproj stream with depth-1 prefetch
    const float* xpp = g_xproj + (long long)b * 24;
    float4 xc[6], xn[6];
    if (l == 0 && bok) {
        #pragma unroll
        for (int j = 0; j < 6; j++) xc[j] = __ldcg((const float4*)xpp + j);
        xpp += NB * 24;
    }

    #pragma unroll 1
    for (int i = 0; i < NS + NL - 1; i++) {
        const int t = i - l;
        const bool active = bok && (t >= 0) && (t < NS);

        // ---- read phase (before barrier 1) ----
        float xk[8];
        if (l > 0 && active) {
            const float4* hin = (const float4*)(shb + (l - 1) * 64 + col * 8);
            float4 a = hin[0], d = hin[1];
            xk[0] = a.x; xk[1] = a.y; xk[2] = a.z; xk[3] = a.w;
            xk[4] = d.x; xk[5] = d.y; xk[6] = d.z; xk[7] = d.w;
        }
        if (l == 0 && bok && (t + 1 < NS)) {
            #pragma unroll
            for (int j = 0; j < 6; j++) xn[j] = __ldcg((const float4*)xpp + j);
            xpp += NB * 24;
        }
        __syncthreads();   // all reads of shb done before writers update it

        // ---- compute + write phase ----
        if (active) {
            u64 az[4], ar[4], aH[4];
            if (l == 0) {
                az[0] = pkab(xc[0].x, xc[0].y); az[1] = pkab(xc[0].z, xc[0].w);
                az[2] = pkab(xc[1].x, xc[1].y); az[3] = pkab(xc[1].z, xc[1].w);
                ar[0] = pkab(xc[2].x, xc[2].y); ar[1] = pkab(xc[2].z, xc[2].w);
                ar[2] = pkab(xc[3].x, xc[3].y); ar[3] = pkab(xc[3].z, xc[3].w);
                aH[0] = pkab(xc[4].x, xc[4].y); aH[1] = pkab(xc[4].z, xc[4].w);
                aH[2] = pkab(xc[5].x, xc[5].y); aH[3] = pkab(xc[5].z, xc[5].w);
            } else {
                #pragma unroll
                for (int j = 0; j < 4; j++) { az[j] = b2[j]; ar[j] = b2[4 + j]; aH[j] = b2[8 + j]; }
                #pragma unroll
                for (int k = 0; k < 8; k++) {
                    const u64 x2 = pk2(xk[k]);
                    fma8w(az, x2, wb + k * 8);             // Wxz
                    fma8w(ar, x2, wb + 128 + k * 8);       // Wxr
                    fma8w(aH, x2, wb + 256 + k * 8);       // WxH
                }
            }
            #pragma unroll
            for (int k = 0; k < 8; k++) {
                const u64 h2 = pk2(h[k]);
                fma8w(az, h2, wb + 64 + k * 8);            // Whz
                fma8w(ar, h2, wb + 192 + k * 8);           // Whr
            }
            float azf[8], arf[8], z[8], r[8];
            #pragma unroll
            for (int j = 0; j < 4; j++) { upk(az[j], azf[2*j], azf[2*j+1]);
                                          upk(ar[j], arf[2*j], arf[2*j+1]); }
            #pragma unroll
            for (int j = 0; j < 8; j++) { z[j] = sigm(azf[j]); r[j] = sigm(arf[j]); }
            #pragma unroll
            for (int k = 0; k < 8; k++) fma8w(aH, pk2(h[k] * r[k]), wb + 320 + k * 8);  // WrH
            float aHf[8];
            #pragma unroll
            for (int j = 0; j < 4; j++) upk(aH[j], aHf[2*j], aHf[2*j+1]);
            #pragma unroll
            for (int j = 0; j < 8; j++) {
                const float Hc = tanh_hw(aHf[j]);
                h[j] = fmaf(z[j], Hc - h[j], h[j]);
            }
            // handoff write (consumed by thread l+1 next iteration)
            if (l < NL - 1) {
                float4* hop = (float4*)(shb + l * 64 + col * 8);
                hop[0] = make_float4(h[0], h[1], h[2], h[3]);
                hop[1] = make_float4(h[4], h[5], h[6], h[7]);
            }
            // final outputs at this thread's last step
            if (t == NS - 1) {
                if (out_size >= NB + NL * NB * HD) {
                    float4* hp = (float4*)(out + NB + ((long long)l * NB + b) * HD);
                    hp[0] = make_float4(h[0], h[1], h[2], h[3]);
                    hp[1] = make_float4(h[4], h[5], h[6], h[7]);
                }
                if (l == NL - 1) {
                    float acc = by[0];
                    #pragma unroll
                    for (int j = 0; j < 8; j++) acc = fmaf(h[j], Why[j], acc);
                    out[b] = acc;
                }
            }
        }
        __syncthreads();   // writes visible to next iteration's readers

        if (l == 0) {
            #pragma unroll
            for (int j = 0; j < 6; j++) xc[j] = xn[j];
        }
    }
}

extern "C" void kernel_launch(void* const* d_in, const int* in_sizes, int n_in,
                              void* d_out, int out_size) {
    const int*   x    = (const int*)d_in[0];
    const float* emb  = (const float*)d_in[1];
    const float* Wxz0 = (const float*)d_in[2];
    const float* Whz0 = (const float*)d_in[3];
    const float* bz0  = (const float*)d_in[4];
    const float* Wxr0 = (const float*)d_in[5];
    const float* Whr0 = (const float*)d_in[6];
    const float* br0  = (const float*)d_in[7];
    const float* WxH0 = (const float*)d_in[8];
    const float* WrH0 = (const float*)d_in[9];
    const float* bH0  = (const float*)d_in[10];
    const float* Wxz  = (const float*)d_in[11];
    const float* Whz  = (const float*)d_in[12];
    const float* bz   = (const float*)d_in[13];
    const float* Wxr  = (const float*)d_in[14];
    const float* Whr  = (const float*)d_in[15];
    const float* br   = (const float*)d_in[16];
    const float* WxH  = (const float*)d_in[17];
    const float* WrH  = (const float*)d_in[18];
    const float* bH   = (const float*)d_in[19];
    const float* Why  = (const float*)d_in[20];
    const float* by   = (const float*)d_in[21];
    float* out = (float*)d_out;

    precompute_xproj<<<(NB * NS + 255) / 256, 256>>>(x, emb, Wxz0, bz0, Wxr0, br0, WxH0, bH0);
    gru_wave<<<GRID, TPB>>>(Whz0, Whr0, WrH0,
                            Wxz, Whz, bz, Wxr, Whr, br, WxH, WrH, bH,
                            Why, by, out, out_size);
}